// round 3
// baseline (speedup 1.0000x reference)
#include <cuda_runtime.h>
#include <cstdint>

// ---------------------------------------------------------------------------
// Problem constants
// ---------------------------------------------------------------------------
constexpr int    N_USERS = 100000;
constexpr int    DIM     = 128;
constexpr size_t SEG     = (size_t)N_USERS * DIM;

// Scratch: 4 slots (LI_u, L_u, LI_i, L_i), each [100000,128] fp32.
__device__ float g_scratch[4ull * 100000ull * 128ull];

// ---------------------------------------------------------------------------
// Kernel 1: zero all scratch
// ---------------------------------------------------------------------------
__global__ void zero_scratch(size_t n4) {
    float4* p = reinterpret_cast<float4*>(g_scratch);
    size_t i = (size_t)blockIdx.x * blockDim.x + threadIdx.x;
    size_t stride = (size_t)gridDim.x * blockDim.x;
    float4 z = make_float4(0.f, 0.f, 0.f, 0.f);
    for (; i < n4; i += stride) p[i] = z;
}

// ---------------------------------------------------------------------------
// Kernel 2: all four SpMMs in one launch (unchanged — passed in R1)
// ---------------------------------------------------------------------------
__device__ __forceinline__ void red_add_v4(float* dst, float x, float y, float z, float w) {
    asm volatile("red.global.add.v4.f32 [%0], {%1, %2, %3, %4};"
                 :: "l"(dst), "f"(x), "f"(y), "f"(z), "f"(w) : "memory");
}

__global__ void __launch_bounds__(256) spmm4(
    const float* __restrict__ ebs,
    const int* __restrict__ r0, const int* __restrict__ c0, const float* __restrict__ v0,
    const int* __restrict__ r1, const int* __restrict__ c1, const float* __restrict__ v1,
    const int* __restrict__ r2, const int* __restrict__ c2, const float* __restrict__ v2,
    const int* __restrict__ r3, const int* __restrict__ c3, const float* __restrict__ v3,
    int nnz)
{
    const int slot = blockIdx.y;
    const int* rows; const int* cols; const float* vals;
    switch (slot) {
        case 0:  rows = r0; cols = c0; vals = v0; break;
        case 1:  rows = r1; cols = c1; vals = v1; break;
        case 2:  rows = r2; cols = c2; vals = v2; break;
        default: rows = r3; cols = c3; vals = v3; break;
    }
    float* out = g_scratch + (size_t)slot * SEG;

    const int lane    = threadIdx.x & 31;
    const int warp_id = (blockIdx.x * blockDim.x + threadIdx.x) >> 5;
    const int base    = warp_id * 32;
    if (base >= nnz) return;
    const int cnt = min(32, nnz - base);

    int r = 0, c = 0; float v = 0.f;
    if (lane < cnt) {
        r = rows[base + lane];
        c = cols[base + lane];
        v = vals[base + lane];
    }

    #pragma unroll 4
    for (int j = 0; j < cnt; j++) {
        const int   rj = __shfl_sync(0xffffffffu, r, j);
        const int   cj = __shfl_sync(0xffffffffu, c, j);
        const float vj = __shfl_sync(0xffffffffu, v, j);
        const float4 e = *reinterpret_cast<const float4*>(ebs + (size_t)cj * DIM + lane * 4);
        float* dst = out + (size_t)rj * DIM + lane * 4;
        red_add_v4(dst, e.x * vj, e.y * vj, e.z * vj, e.w * vj);
    }
}

// ---------------------------------------------------------------------------
// Kernel 3: tf32 mma.sync fused fold GEMM with error compensation.
//   out = leaky( [LI | L*ent] @ [Ws ; Wd] ),  K=256 in 8 chunks of 32.
//   C += Ah@Bh + Al@Bh + Ah@Bl  (hi/lo tf32 split; missing Al@Bl ~ 2^-22)
// Block: 256 thr (8 warps), tile 128x128. Warp tile 32x64 (2 m-atoms, 8 n-atoms).
// Smem: hi/lo A and B chunks, double buffered (128 KB). Fragments are stored
// in smem pre-shuffled into the exact m16n8k8 lane layout -> LDS.128/LDS.64.
// ---------------------------------------------------------------------------
constexpr int TILES_PER_FOLD = (N_USERS + 127) / 128;   // 782

__device__ __forceinline__ uint32_t f2tf32(float f) {
    uint32_t r;
    asm("cvt.rna.tf32.f32 %0, %1;" : "=r"(r) : "f"(f));
    return r;
}

__device__ __forceinline__ void mma_tf32(float* c, const uint32_t* a, const uint32_t* b) {
    asm volatile(
        "mma.sync.aligned.m16n8k8.row.col.f32.tf32.tf32.f32 "
        "{%0,%1,%2,%3}, {%4,%5,%6,%7}, {%8,%9}, {%0,%1,%2,%3};"
        : "+f"(c[0]), "+f"(c[1]), "+f"(c[2]), "+f"(c[3])
        : "r"(a[0]), "r"(a[1]), "r"(a[2]), "r"(a[3]), "r"(b[0]), "r"(b[1]));
}

// smem float counts
constexpr int ACH = 4096;      // one A chunk: 128 rows x 32 k
constexpr int BCH = 4096;      // one B chunk: 32 k x 128 n
constexpr int SMEM_FLOATS = 2 * ACH * 2 + 2 * BCH * 2;   // Ah,Al,Bh,Bl x2 buf
constexpr int GEMM_SMEM = SMEM_FLOATS * 4;               // 131072 B

__global__ void __launch_bounds__(256, 1) fold_gemm_mma(
    const float* __restrict__ ebs,
    const float* __restrict__ Wsu, const float* __restrict__ Wdu,
    const float* __restrict__ Wsi, const float* __restrict__ Wdi,
    float* __restrict__ outp)
{
    extern __shared__ float sm[];
    float* Ah = sm;                   // [2][ACH]
    float* Al = Ah + 2 * ACH;
    float* Bh = Al + 2 * ACH;         // [2][BCH]
    float* Bl = Bh + 2 * BCH;

    const int tid  = threadIdx.x;
    const int wid  = tid >> 5;
    const int lane = tid & 31;
    const int wm   = wid & 3;         // warp row group (32 rows each)
    const int wn   = wid >> 2;        // warp col group (64 cols each)

    const int fold = blockIdx.y;
    const int row0 = blockIdx.x * 128;

    const float* LI  = g_scratch + (size_t)(2 * fold)     * SEG;
    const float* L   = g_scratch + (size_t)(2 * fold + 1) * SEG;
    const float* ent = ebs  + (size_t)fold * SEG;
    const float* Ws  = fold ? Wsi : Wsu;
    const float* Wd  = fold ? Wdi : Wdu;
    float* out       = outp + (size_t)fold * SEG;

    float acc[2][8][4];
    #pragma unroll
    for (int i = 0; i < 2; i++)
        #pragma unroll
        for (int j = 0; j < 8; j++)
            #pragma unroll
            for (int q = 0; q < 4; q++) acc[i][j][q] = 0.f;

    float4 prefA[4], prefB[4];

    // ---- chunk loaders (global -> regs) ----
    auto loadA = [&](int kc) {
        const float* s0 = (kc < 4) ? LI : L;
        const bool  gate = (kc >= 4);
        const int   cb   = (kc & 3) * 32;
        #pragma unroll
        for (int i = 0; i < 4; i++) {
            const int idx = i * 256 + tid;         // 0..1023
            const int r   = idx >> 3;              // 0..127
            const int k4  = idx & 7;               // float4 index along k
            float4 v = make_float4(0.f, 0.f, 0.f, 0.f);
            const int grow = row0 + r;
            if (grow < N_USERS) {
                v = *reinterpret_cast<const float4*>(s0 + (size_t)grow * DIM + cb + k4 * 4);
                if (gate) {
                    const float4 e = *reinterpret_cast<const float4*>(ent + (size_t)grow * DIM + cb + k4 * 4);
                    v.x *= e.x; v.y *= e.y; v.z *= e.z; v.w *= e.w;
                }
            }
            prefA[i] = v;
        }
    };
    auto loadB = [&](int kc) {
        const float* Wsrc = (kc < 4) ? Ws : Wd;
        const int kb = (kc & 3) * 32;
        #pragma unroll
        for (int i = 0; i < 4; i++) {
            const int idx = i * 256 + tid;
            const int k   = idx >> 5;              // 0..31
            const int n4  = idx & 31;
            prefB[i] = *reinterpret_cast<const float4*>(Wsrc + (size_t)(kb + k) * DIM + n4 * 4);
        }
    };

    // ---- regs -> smem with tf32 hi/lo split, pre-shuffled fragment layout ----
    auto stsA = [&](int b) {
        float* ah = Ah + b * ACH;
        float* al = Al + b * ACH;
        #pragma unroll
        for (int i = 0; i < 4; i++) {
            const int idx = i * 256 + tid;
            const int r   = idx >> 3;
            const int k4  = idx & 7;
            const int m16 = r >> 4;
            const int rr  = r & 15;
            const int ks  = k4 >> 1;                       // kstep 0..3
            const int slot = ((k4 & 1) << 1) | ((rr & 8) >> 3);
            const int base = ((ks * 8 + m16) * 32) * 4 + slot;
            const int lane0 = (rr & 7) * 4;
            const float vv[4] = {prefA[i].x, prefA[i].y, prefA[i].z, prefA[i].w};
            #pragma unroll
            for (int j = 0; j < 4; j++) {
                const uint32_t hb = f2tf32(vv[j]);
                const float    hf = __uint_as_float(hb);
                const uint32_t lb = f2tf32(vv[j] - hf);
                const int off = base + (lane0 + j) * 4;
                ah[off] = hf;
                al[off] = __uint_as_float(lb);
            }
        }
    };
    auto stsB = [&](int b) {
        float* bh = Bh + b * BCH;
        float* bl = Bl + b * BCH;
        #pragma unroll
        for (int i = 0; i < 4; i++) {
            const int idx = i * 256 + tid;
            const int k   = idx >> 5;
            const int n0  = (idx & 31) * 4;
            const int ks  = k >> 3;
            const int kk  = k & 7;
            const int slot = (kk & 4) >> 2;
            const float vv[4] = {prefB[i].x, prefB[i].y, prefB[i].z, prefB[i].w};
            #pragma unroll
            for (int j = 0; j < 4; j++) {
                const int n = n0 + j;
                const int laneB = (n & 7) * 4 + (kk & 3);
                const int off = ((ks * 16 + (n >> 3)) * 32 + laneB) * 2 + slot;
                const uint32_t hb = f2tf32(vv[j]);
                const float    hf = __uint_as_float(hb);
                const uint32_t lb = f2tf32(vv[j] - hf);
                bh[off] = hf;
                bl[off] = __uint_as_float(lb);
            }
        }
    };

    // ---- compute one 32-k chunk from buffer b ----
    auto compute = [&](int b) {
        const float* ah = Ah + b * ACH;
        const float* al = Al + b * ACH;
        const float* bh = Bh + b * BCH;
        const float* bl = Bl + b * BCH;
        #pragma unroll
        for (int s = 0; s < 4; s++) {
            uint32_t afh[2][4], afl[2][4];
            #pragma unroll
            for (int i = 0; i < 2; i++) {
                const int off = ((s * 8 + (wm * 2 + i)) * 32 + lane) * 4;
                *reinterpret_cast<uint4*>(afh[i]) = *reinterpret_cast<const uint4*>(ah + off);
                *reinterpret_cast<uint4*>(afl[i]) = *reinterpret_cast<const uint4*>(al + off);
            }
            uint32_t bfh[8][2], bfl[8][2];
            #pragma unroll
            for (int j = 0; j < 8; j++) {
                const int off = ((s * 16 + (wn * 8 + j)) * 32 + lane) * 2;
                *reinterpret_cast<uint2*>(bfh[j]) = *reinterpret_cast<const uint2*>(bh + off);
                *reinterpret_cast<uint2*>(bfl[j]) = *reinterpret_cast<const uint2*>(bl + off);
            }
            #pragma unroll
            for (int i = 0; i < 2; i++)
                #pragma unroll
                for (int j = 0; j < 8; j++) {
                    mma_tf32(acc[i][j], afh[i], bfh[j]);   // Ah@Bh
                    mma_tf32(acc[i][j], afl[i], bfh[j]);   // Al@Bh
                    mma_tf32(acc[i][j], afh[i], bfl[j]);   // Ah@Bl
                }
        }
    };

    // ---- pipelined main loop over 8 K-chunks ----
    loadA(0); loadB(0);
    #pragma unroll 1
    for (int kc = 0; kc < 8; kc++) {
        const int b = kc & 1;
        stsA(b); stsB(b);
        __syncthreads();
        if (kc < 7) { loadA(kc + 1); loadB(kc + 1); }
        compute(b);
        __syncthreads();
    }

    // ---- epilogue: leaky relu + store ----
    const int g  = lane >> 2;
    const int tg = lane & 3;
    #pragma unroll
    for (int i = 0; i < 2; i++) {
        const int r_lo = row0 + wm * 32 + i * 16 + g;
        const int r_hi = r_lo + 8;
        #pragma unroll
        for (int j = 0; j < 8; j++) {
            const int col = wn * 64 + j * 8 + 2 * tg;
            float x;
            float2 o;
            if (r_lo < N_USERS) {
                x = acc[i][j][0]; o.x = (x > 0.f) ? x : 0.2f * x;
                x = acc[i][j][1]; o.y = (x > 0.f) ? x : 0.2f * x;
                *reinterpret_cast<float2*>(out + (size_t)r_lo * DIM + col) = o;
            }
            if (r_hi < N_USERS) {
                x = acc[i][j][2]; o.x = (x > 0.f) ? x : 0.2f * x;
                x = acc[i][j][3]; o.y = (x > 0.f) ? x : 0.2f * x;
                *reinterpret_cast<float2*>(out + (size_t)r_hi * DIM + col) = o;
            }
        }
    }
}

// ---------------------------------------------------------------------------
// Launch contract
// ---------------------------------------------------------------------------
extern "C" void kernel_launch(void* const* d_in, const int* in_sizes, int n_in,
                              void* d_out, int out_size)
{
    const float* ebs  = (const float*)d_in[0];
    const float* Wsu  = (const float*)d_in[1];
    const float* Wdu  = (const float*)d_in[2];
    const float* Wsi  = (const float*)d_in[3];
    const float* Wdi  = (const float*)d_in[4];
    const float* vLIu = (const float*)d_in[5];
    const float* vLu  = (const float*)d_in[6];
    const float* vLIi = (const float*)d_in[7];
    const float* vLi  = (const float*)d_in[8];
    const int* rLIu = (const int*)d_in[9];
    const int* cLIu = (const int*)d_in[10];
    const int* rLu  = (const int*)d_in[11];
    const int* cLu  = (const int*)d_in[12];
    const int* rLIi = (const int*)d_in[13];
    const int* cLIi = (const int*)d_in[14];
    const int* rLi  = (const int*)d_in[15];
    const int* cLi  = (const int*)d_in[16];
    float* out = (float*)d_out;

    const int nnz = in_sizes[5];

    // 1) zero scratch
    zero_scratch<<<6250, 256>>>(4 * SEG / 4);

    // 2) four SpMMs in one launch
    {
        const int warps  = (nnz + 31) / 32;
        const int blocks = (warps + 7) / 8;
        dim3 grid(blocks, 4);
        spmm4<<<grid, 256>>>(ebs,
                             rLIu, cLIu, vLIu,
                             rLu,  cLu,  vLu,
                             rLIi, cLIi, vLIi,
                             rLi,  cLi,  vLi,
                             nnz);
    }

    // 3) tf32 mma.sync fused fold GEMM
    {
        cudaFuncSetAttribute(fold_gemm_mma,
                             cudaFuncAttributeMaxDynamicSharedMemorySize, GEMM_SMEM);
        dim3 grid(TILES_PER_FOLD, 2);
        fold_gemm_mma<<<grid, 256, GEMM_SMEM>>>(ebs, Wsu, Wdu, Wsi, Wdi, out);
    }
}

// round 4
// speedup vs baseline: 1.6424x; 1.6424x over previous
#include <cuda_runtime.h>
#include <cstdint>

// ---------------------------------------------------------------------------
// Problem constants
// ---------------------------------------------------------------------------
constexpr int    N_USERS = 100000;
constexpr int    DIM     = 128;
constexpr size_t SEG     = (size_t)N_USERS * DIM;
constexpr int    NROWS   = 100000;        // rows per SpMM output
constexpr int    NSLOT   = 4;             // LI_u, L_u, LI_i, L_i
constexpr int    CAP     = 64;            // bucket capacity (Poisson(10) tail ~1e-30)

// Scratch SpMM outputs: 4 x [100000,128] fp32.
__device__ float g_scratch[(size_t)NSLOT * NROWS * DIM];
// Per-row nnz counters and buckets (col, val-bits) interleaved.
__device__ int  g_cnt[NSLOT * NROWS];
__device__ int2 g_bucket[(size_t)NSLOT * NROWS * CAP];

// ---------------------------------------------------------------------------
// f32x2 packed-FMA helpers (PTX ISA 8.6, sm_100+; SASS FFMA2 path)
// ---------------------------------------------------------------------------
__device__ __forceinline__ unsigned long long pk2(float x, float y) {
    unsigned long long r;
    asm("mov.b64 %0, {%1, %2};" : "=l"(r) : "r"(__float_as_uint(x)), "r"(__float_as_uint(y)));
    return r;
}
__device__ __forceinline__ unsigned long long fma2(unsigned long long a,
                                                   unsigned long long b,
                                                   unsigned long long c) {
    unsigned long long d;
    asm("fma.rn.f32x2 %0, %1, %2, %3;" : "=l"(d) : "l"(a), "l"(b), "l"(c));
    return d;
}
__device__ __forceinline__ void upk2(unsigned long long v, float& lo, float& hi) {
    uint32_t a, b;
    asm("mov.b64 {%0, %1}, %2;" : "=r"(a), "=r"(b) : "l"(v));
    lo = __uint_as_float(a); hi = __uint_as_float(b);
}

// ---------------------------------------------------------------------------
// Kernel 1: zero the per-row counters (tiny)
// ---------------------------------------------------------------------------
__global__ void zero_cnt() {
    int i = blockIdx.x * blockDim.x + threadIdx.x;
    if (i < NSLOT * NROWS) g_cnt[i] = 0;
}

// ---------------------------------------------------------------------------
// Kernel 2: scatter nnz into per-row buckets. blockIdx.y selects matrix.
// ---------------------------------------------------------------------------
__global__ void __launch_bounds__(256) scatter_nnz(
    const int* __restrict__ r0, const int* __restrict__ c0, const float* __restrict__ v0,
    const int* __restrict__ r1, const int* __restrict__ c1, const float* __restrict__ v1,
    const int* __restrict__ r2, const int* __restrict__ c2, const float* __restrict__ v2,
    const int* __restrict__ r3, const int* __restrict__ c3, const float* __restrict__ v3,
    int nnz)
{
    const int slot = blockIdx.y;
    const int* rows; const int* cols; const float* vals;
    switch (slot) {
        case 0:  rows = r0; cols = c0; vals = v0; break;
        case 1:  rows = r1; cols = c1; vals = v1; break;
        case 2:  rows = r2; cols = c2; vals = v2; break;
        default: rows = r3; cols = c3; vals = v3; break;
    }
    const int i = blockIdx.x * 256 + threadIdx.x;
    if (i >= nnz) return;
    const int   row = rows[i];
    const int   col = cols[i];
    const float val = vals[i];
    const int gr  = slot * NROWS + row;
    const int pos = atomicAdd(&g_cnt[gr], 1);
    if (pos < CAP)   // never triggers for Poisson(10) rows; bounded for safety
        g_bucket[(size_t)gr * CAP + pos] = make_int2(col, __float_as_int(val));
}

// ---------------------------------------------------------------------------
// Kernel 3: gather — one warp per output row; register accumulate; clean store.
// ---------------------------------------------------------------------------
__global__ void __launch_bounds__(256) gather_rows(const float* __restrict__ ebs)
{
    const int wg   = (blockIdx.x * 256 + threadIdx.x) >> 5;   // global warp = row id
    const int lane = threadIdx.x & 31;
    if (wg >= NSLOT * NROWS) return;

    int cnt = g_cnt[wg];
    cnt = min(cnt, CAP);

    const int2* bk = g_bucket + (size_t)wg * CAP;
    int2 e0 = make_int2(0, 0), e1 = make_int2(0, 0);
    if (lane      < cnt) e0 = bk[lane];
    if (lane + 32 < cnt) e1 = bk[lane + 32];

    float4 acc = make_float4(0.f, 0.f, 0.f, 0.f);
    for (int j = 0; j < cnt; j++) {
        int cj, vb;
        if (j < 32) { cj = __shfl_sync(0xffffffffu, e0.x, j);
                      vb = __shfl_sync(0xffffffffu, e0.y, j); }
        else        { cj = __shfl_sync(0xffffffffu, e1.x, j - 32);
                      vb = __shfl_sync(0xffffffffu, e1.y, j - 32); }
        const float  vj = __int_as_float(vb);
        const float4 e  = *reinterpret_cast<const float4*>(ebs + (size_t)cj * DIM + lane * 4);
        acc.x += vj * e.x; acc.y += vj * e.y; acc.z += vj * e.z; acc.w += vj * e.w;
    }
    *reinterpret_cast<float4*>(g_scratch + (size_t)wg * DIM + lane * 4) = acc;
}

// ---------------------------------------------------------------------------
// Kernel 4: fused fold GEMM + gate + leaky relu, f32x2 packed FMA.
//   out = leaky( LI @ Ws + (L*ent) @ Wd )
// Block 256 thr, tile 32 rows x 128 cols, thread microtile 4x4 (2 f32x2 pairs).
// ---------------------------------------------------------------------------
constexpr int TR = 32;

__global__ void __launch_bounds__(256) fold_gemm2(
    const float* __restrict__ ebs,
    const float* __restrict__ Wsu, const float* __restrict__ Wdu,
    const float* __restrict__ Wsi, const float* __restrict__ Wdi,
    float* __restrict__ outp)
{
    const int fold = blockIdx.y;
    const float* LI  = g_scratch + (size_t)(2 * fold)     * SEG;
    const float* L   = g_scratch + (size_t)(2 * fold + 1) * SEG;
    const float* ent = ebs  + (size_t)fold * SEG;
    const float* Ws  = fold ? Wsi : Wsu;
    const float* Wd  = fold ? Wdi : Wdu;
    float* out       = outp + (size_t)fold * SEG;

    __shared__ float As[TR][DIM];   // LI rows
    __shared__ float Bs[TR][DIM];   // (L * ent) rows

    const int row0 = blockIdx.x * TR;
    const int tid  = threadIdx.x;

    for (int i = tid; i < TR * (DIM / 4); i += 256) {
        const int rr = i >> 5;
        const int c4 = i & 31;
        const size_t g = (size_t)(row0 + rr) * DIM + c4 * 4;
        const float4 li = *reinterpret_cast<const float4*>(LI  + g);
        const float4 ll = *reinterpret_cast<const float4*>(L   + g);
        const float4 ee = *reinterpret_cast<const float4*>(ent + g);
        *reinterpret_cast<float4*>(&As[rr][c4 * 4]) = li;
        float4 b = make_float4(ll.x * ee.x, ll.y * ee.y, ll.z * ee.z, ll.w * ee.w);
        *reinterpret_cast<float4*>(&Bs[rr][c4 * 4]) = b;
    }
    __syncthreads();

    const int tx = tid & 31;   // cols 4*tx .. 4*tx+3
    const int ty = tid >> 5;   // rows 4*ty .. 4*ty+3

    unsigned long long acc2[4][2];
    #pragma unroll
    for (int r = 0; r < 4; r++) { acc2[r][0] = 0ull; acc2[r][1] = 0ull; }

    #pragma unroll 8
    for (int kb = 0; kb < DIM; kb += 4) {
        float4 a4[4], b4[4];
        #pragma unroll
        for (int r = 0; r < 4; r++) {
            a4[r] = *reinterpret_cast<const float4*>(&As[ty * 4 + r][kb]);
            b4[r] = *reinterpret_cast<const float4*>(&Bs[ty * 4 + r][kb]);
        }
        #pragma unroll
        for (int kk = 0; kk < 4; kk++) {
            const int k = kb + kk;
            // two packed f32 pairs per W row, straight from memory as u64 bits
            const ulonglong2 wsp = *reinterpret_cast<const ulonglong2*>(Ws + (size_t)k * DIM + tx * 4);
            const ulonglong2 wdp = *reinterpret_cast<const ulonglong2*>(Wd + (size_t)k * DIM + tx * 4);
            #pragma unroll
            for (int r = 0; r < 4; r++) {
                const float av = (kk == 0) ? a4[r].x : (kk == 1) ? a4[r].y : (kk == 2) ? a4[r].z : a4[r].w;
                const float bv = (kk == 0) ? b4[r].x : (kk == 1) ? b4[r].y : (kk == 2) ? b4[r].z : b4[r].w;
                const unsigned long long aa = pk2(av, av);
                const unsigned long long bb = pk2(bv, bv);
                acc2[r][0] = fma2(aa, wsp.x, acc2[r][0]);
                acc2[r][1] = fma2(aa, wsp.y, acc2[r][1]);
                acc2[r][0] = fma2(bb, wdp.x, acc2[r][0]);
                acc2[r][1] = fma2(bb, wdp.y, acc2[r][1]);
            }
        }
    }

    #pragma unroll
    for (int r = 0; r < 4; r++) {
        float c0, c1, c2, c3;
        upk2(acc2[r][0], c0, c1);
        upk2(acc2[r][1], c2, c3);
        float4 o;
        o.x = (c0 > 0.f) ? c0 : 0.2f * c0;
        o.y = (c1 > 0.f) ? c1 : 0.2f * c1;
        o.z = (c2 > 0.f) ? c2 : 0.2f * c2;
        o.w = (c3 > 0.f) ? c3 : 0.2f * c3;
        *reinterpret_cast<float4*>(out + (size_t)(row0 + ty * 4 + r) * DIM + tx * 4) = o;
    }
}

// ---------------------------------------------------------------------------
// Launch contract
// ---------------------------------------------------------------------------
extern "C" void kernel_launch(void* const* d_in, const int* in_sizes, int n_in,
                              void* d_out, int out_size)
{
    const float* ebs  = (const float*)d_in[0];
    const float* Wsu  = (const float*)d_in[1];
    const float* Wdu  = (const float*)d_in[2];
    const float* Wsi  = (const float*)d_in[3];
    const float* Wdi  = (const float*)d_in[4];
    const float* vLIu = (const float*)d_in[5];
    const float* vLu  = (const float*)d_in[6];
    const float* vLIi = (const float*)d_in[7];
    const float* vLi  = (const float*)d_in[8];
    const int* rLIu = (const int*)d_in[9];
    const int* cLIu = (const int*)d_in[10];
    const int* rLu  = (const int*)d_in[11];
    const int* cLu  = (const int*)d_in[12];
    const int* rLIi = (const int*)d_in[13];
    const int* cLIi = (const int*)d_in[14];
    const int* rLi  = (const int*)d_in[15];
    const int* cLi  = (const int*)d_in[16];
    float* out = (float*)d_out;

    const int nnz = in_sizes[5];   // 1,000,000

    // 1) zero counters
    zero_cnt<<<(NSLOT * NROWS + 255) / 256, 256>>>();

    // 2) scatter nnz into buckets (4 matrices via grid.y)
    {
        dim3 grid((nnz + 255) / 256, NSLOT);
        scatter_nnz<<<grid, 256>>>(rLIu, cLIu, vLIu,
                                   rLu,  cLu,  vLu,
                                   rLIi, cLIi, vLIi,
                                   rLi,  cLi,  vLi,
                                   nnz);
    }

    // 3) gather: one warp per output row, atomic-free accumulation
    {
        const int total_warps = NSLOT * NROWS;                // 400,000
        const int blocks = (total_warps * 32 + 255) / 256;    // 50,000
        gather_rows<<<blocks, 256>>>(ebs);
    }

    // 4) fused fold GEMM (f32x2 packed FMA), both folds
    {
        dim3 grid(N_USERS / TR, 2);
        fold_gemm2<<<grid, 256>>>(ebs, Wsu, Wdu, Wsi, Wdi, out);
    }
}